// round 3
// baseline (speedup 1.0000x reference)
#include <cuda_runtime.h>
#include <cstdint>

// PixelShuffle / depth-to-space, R=2, feature-major channel grouping.
//   out[b, 2x+i, 2y+j, f] = in[b, x, y, 4f + 2i + j]
// in : [B=8, X=256, Y=256, C=256] fp32   (512 MiB)
// out: [B=8, 512, 512, 64]        fp32   (512 MiB)
//
// Pure streaming permutation; HBM-bound. v2 changes vs v1 (149.6us, 86% DRAM):
//  - 8 input float4s per thread (one thread = 8 consecutive features,
//    half-warp = one full 1 KiB input pixel -> each half-warp's loads are a
//    single contiguous 512 B run; MLP_p1 = 8).
//  - __ldcs / __stcs: zero-reuse data, evict-first in both directions.
// Each output quadrant store per thread is 2 consecutive float4s (32 B);
// a half-warp's quadrant store instruction covers a contiguous 256 B run.

static constexpr int B_ = 8;
static constexpr int X_ = 256;
static constexpr int Y_ = 256;
static constexpr int C_ = 256;              // 64 features * 4
static constexpr int F4_PER_PIX_OUT = 16;   // 64 feat / 4
static constexpr int THREADS_PER_PIX = 8;   // each thread covers 32 input channels

__global__ __launch_bounds__(256)
void pixelshuffle_kernel(const float4* __restrict__ in, float4* __restrict__ out) {
    unsigned g = blockIdx.x * blockDim.x + threadIdx.x;
    unsigned t     = g & (THREADS_PER_PIX - 1);   // 0..7
    unsigned pixel = g >> 3;                      // input pixel id, < B*X*Y

    unsigned y = pixel & (Y_ - 1);
    unsigned x = (pixel >> 8) & (X_ - 1);
    unsigned b = pixel >> 16;

    // Thread t reads float4s [8t .. 8t+7] of this pixel's 64-float4 row:
    // channels 32t..32t+31 = features 8t..8t+7. Contiguous 128 B per thread.
    const float4* src = in + (size_t)pixel * (C_ / 4) + (size_t)t * 8;
    float4 v[8];
#pragma unroll
    for (int k = 0; k < 8; k++) v[k] = __ldcs(src + k);

    // Output float4 index: ((b*512 + 2x+i)*512 + 2y+j)*16 + 2t + {0,1}
    size_t ob = (((size_t)b * (2 * X_) + 2 * x) * (2 * Y_) + 2 * y) * F4_PER_PIX_OUT
              + (size_t)t * 2;
    const size_t ROW = (size_t)(2 * Y_) * F4_PER_PIX_OUT;  // output row, in float4s

    // quadrant component index = 2i + j
    // j=0,i=0 -> .x ; j=1,i=0 -> .y ; j=0,i=1 -> .z ; j=1,i=1 -> .w
    __stcs(out + ob,                make_float4(v[0].x, v[1].x, v[2].x, v[3].x));
    __stcs(out + ob + 1,            make_float4(v[4].x, v[5].x, v[6].x, v[7].x));
    __stcs(out + ob + 16,           make_float4(v[0].y, v[1].y, v[2].y, v[3].y));
    __stcs(out + ob + 17,           make_float4(v[4].y, v[5].y, v[6].y, v[7].y));
    __stcs(out + ob + ROW,          make_float4(v[0].z, v[1].z, v[2].z, v[3].z));
    __stcs(out + ob + ROW + 1,      make_float4(v[4].z, v[5].z, v[6].z, v[7].z));
    __stcs(out + ob + ROW + 16,     make_float4(v[0].w, v[1].w, v[2].w, v[3].w));
    __stcs(out + ob + ROW + 17,     make_float4(v[4].w, v[5].w, v[6].w, v[7].w));
}

extern "C" void kernel_launch(void* const* d_in, const int* in_sizes, int n_in,
                              void* d_out, int out_size) {
    const float4* in = (const float4*)d_in[0];
    float4* out = (float4*)d_out;

    // total threads = B*X*Y*8 = 4,194,304
    const unsigned n_threads = (unsigned)B_ * X_ * Y_ * THREADS_PER_PIX;
    const unsigned tpb = 256;
    pixelshuffle_kernel<<<n_threads / tpb, tpb>>>(in, out);
}

// round 5
// speedup vs baseline: 1.1554x; 1.1554x over previous
#include <cuda_runtime.h>
#include <cstdint>

// PixelShuffle / depth-to-space, R=2, feature-major channel grouping.
//   out[b, 2x+i, 2y+j, f] = in[b, x, y, 4f + 2i + j]
// in : [B=8, X=256, Y=256, C=256] fp32   (512 MiB)
// out: [B=8, 512, 512, 64]        fp32   (512 MiB)
//
// v3 = v1 structure (149.6us, DRAM 86%, regs 30, occ 80%) + streaming cache
// hints only. v2's 8-wide ILP variant regressed (regs 46 -> occ 52% -> DRAM
// 70%); reverted. Round-4 bench was an infra failure; this is an unchanged
// resubmit of v3.
//
// Layout: 16 threads per input pixel; thread t loads 4 consecutive float4s
// (features 4t..4t+3), register-transposes, stores one float4 per output
// quadrant. Half-warp loads cover a contiguous 512 B run; each quadrant
// store per half-warp is a contiguous 256 B run. All full sectors.

static constexpr int B_ = 8;
static constexpr int X_ = 256;
static constexpr int Y_ = 256;
static constexpr int C_ = 256;              // 64 features * 4
static constexpr int F4_PER_PIX_OUT = 16;   // 64 feat / 4
static constexpr int THREADS_PER_PIX = 16;  // each covers 16 input channels

__global__ __launch_bounds__(256)
void pixelshuffle_kernel(const float4* __restrict__ in, float4* __restrict__ out) {
    unsigned g = blockIdx.x * blockDim.x + threadIdx.x;
    unsigned t     = g & (THREADS_PER_PIX - 1);   // 0..15: feature-quad index
    unsigned pixel = g >> 4;                      // input pixel id, < B*X*Y

    unsigned y = pixel & (Y_ - 1);
    unsigned x = (pixel >> 8) & (X_ - 1);
    unsigned b = pixel >> 16;

    // Input: pixel row is 64 float4s; thread t reads 4 consecutive float4s.
    const float4* src = in + (size_t)pixel * (C_ / 4) + (size_t)t * 4;
    float4 v0 = __ldcs(src + 0);   // feature 4t+0, quadrants in .x/.y/.z/.w
    float4 v1 = __ldcs(src + 1);   // feature 4t+1
    float4 v2 = __ldcs(src + 2);   // feature 4t+2
    float4 v3 = __ldcs(src + 3);   // feature 4t+3

    // Output float4 index: ((b*512 + 2x+i)*512 + 2y+j)*16 + t
    size_t ob = (((size_t)b * (2 * X_) + 2 * x) * (2 * Y_) + 2 * y) * F4_PER_PIX_OUT + t;
    const size_t ROW = (size_t)(2 * Y_) * F4_PER_PIX_OUT;  // one output row of float4s

    // quadrant component index = 2i + j
    __stcs(out + ob,            make_float4(v0.x, v1.x, v2.x, v3.x)); // i=0, j=0
    __stcs(out + ob + 16,       make_float4(v0.y, v1.y, v2.y, v3.y)); // i=0, j=1
    __stcs(out + ob + ROW,      make_float4(v0.z, v1.z, v2.z, v3.z)); // i=1, j=0
    __stcs(out + ob + ROW + 16, make_float4(v0.w, v1.w, v2.w, v3.w)); // i=1, j=1
}

extern "C" void kernel_launch(void* const* d_in, const int* in_sizes, int n_in,
                              void* d_out, int out_size) {
    const float4* in = (const float4*)d_in[0];
    float4* out = (float4*)d_out;

    // total threads = B*X*Y*16 = 8,388,608
    const unsigned n_threads = (unsigned)B_ * X_ * Y_ * THREADS_PER_PIX;
    const unsigned tpb = 256;
    pixelshuffle_kernel<<<n_threads / tpb, tpb>>>(in, out);
}

// round 7
// speedup vs baseline: 1.1573x; 1.0016x over previous
#include <cuda_runtime.h>
#include <cstdint>

// PixelShuffle / depth-to-space, R=2, feature-major channel grouping.
//   out[b, 2x+i, 2y+j, f] = in[b, x, y, 4f + 2i + j]
// in : [B=8, X=256, Y=256, C=256] fp32   (512 MiB)
// out: [B=8, 512, 512, 64]        fp32   (512 MiB)
//
// FINAL-CANDIDATE. Pure streaming permutation, HBM-bound at the mixed
// read+write ceiling: two independent benches measured 6.8 TB/s (86% of
// spec), DRAM% dominant, issue 7%, occ 81%. v2 (8-wide ILP) regressed via
// register pressure; v3 (__ldcs/__stcs) was neutral. v5 = v3 with 32-bit
// indexing (output = 2^27 float4s, fits u32) to trim IMADs/registers.
// Round-6 bench was an infra failure; this is an unchanged resubmit of v5.
//
// Layout: 16 threads per input pixel; thread t loads 4 consecutive float4s
// (features 4t..4t+3), register-transposes, stores one float4 per output
// quadrant. Half-warp loads: contiguous 512 B run; each quadrant store per
// half-warp: contiguous 256 B run. All sectors full.

static constexpr int C_ = 256;              // 64 features * 4
static constexpr int F4_PER_PIX_OUT = 16;   // 64 feat / 4
static constexpr unsigned N_THREADS = 8u * 256u * 256u * 16u;  // B*X*Y*16

__global__ __launch_bounds__(256)
void pixelshuffle_kernel(const float4* __restrict__ in, float4* __restrict__ out) {
    unsigned g = blockIdx.x * blockDim.x + threadIdx.x;
    unsigned t     = g & 15u;    // 0..15: feature-quad index
    unsigned pixel = g >> 4;     // input pixel id, < B*X*Y = 2^19

    unsigned y  = pixel & 255u;          // Y_-1
    unsigned bx = pixel >> 8;            // b*256 + x  (b*X + x)

    // Input: pixel row is 64 float4s; thread t reads 4 consecutive float4s.
    const float4* src = in + pixel * (C_ / 4) + t * 4u;
    float4 v0 = __ldcs(src + 0);   // feature 4t+0, quadrants in .x/.y/.z/.w
    float4 v1 = __ldcs(src + 1);   // feature 4t+1
    float4 v2 = __ldcs(src + 2);   // feature 4t+2
    float4 v3 = __ldcs(src + 3);   // feature 4t+3

    // Output float4 index: ((b*512 + 2x+i)*512 + 2y+j)*16 + t
    //  = (2*bx + i)*8192 + (2y + j)*16 + t      (all fits in u32: max ~2^27)
    unsigned ob = (2u * bx) * 8192u + (2u * y) * 16u + t;
    const unsigned ROW = 8192u;  // one output row of float4s (512*16)

    // quadrant component index = 2i + j
    __stcs(out + ob,            make_float4(v0.x, v1.x, v2.x, v3.x)); // i=0, j=0
    __stcs(out + ob + 16,       make_float4(v0.y, v1.y, v2.y, v3.y)); // i=0, j=1
    __stcs(out + ob + ROW,      make_float4(v0.z, v1.z, v2.z, v3.z)); // i=1, j=0
    __stcs(out + ob + ROW + 16, make_float4(v0.w, v1.w, v2.w, v3.w)); // i=1, j=1
}

extern "C" void kernel_launch(void* const* d_in, const int* in_sizes, int n_in,
                              void* d_out, int out_size) {
    const float4* in = (const float4*)d_in[0];
    float4* out = (float4*)d_out;
    pixelshuffle_kernel<<<N_THREADS / 256u, 256u>>>(in, out);
}

// round 8
// speedup vs baseline: 1.1699x; 1.0109x over previous
#include <cuda_runtime.h>
#include <cstdint>

// PixelShuffle / depth-to-space, R=2, feature-major channel grouping.
//   out[b, 2x+i, 2y+j, f] = in[b, x, y, 4f + 2i + j]
// in : [B=8, X=256, Y=256, C=256] fp32   (512 MiB)
// out: [B=8, 512, 512, 64]        fp32   (512 MiB)
//
// FINAL. Pure streaming permutation at the mixed read+write HBM ceiling:
// three clean measurements at 149.6-150.3us kernel (6.8 TB/s, 85-86% of
// 8 TB/s spec), DRAM% the only saturated resource. Tested and exhausted:
//   v1 16t/pixel float4 transpose    149.6us  (DRAM 86%, regs 30, occ 81%)
//   v2 8t/pixel, 8-wide ILP          182us    REGRESSED (regs 46, occ 52%)
//   v3 v1 + __ldcs/__stcs            150.3us  neutral
//   v5 v3 + u32 indexing             150.0us  neutral (occ 57% -> no effect,
//                                              proving occupancy non-binding)
// Traffic is the mandatory 1 GiB (no reuse, no compression); L2/issue far
// from saturation; HBM striding not a lever on B300. Residual vs spec is
// bus turnaround. Byte-identical resubmit of v5 as final confirmation.
//
// Layout: 16 threads per input pixel; thread t loads 4 consecutive float4s
// (features 4t..4t+3), register-transposes, stores one float4 per output
// quadrant. Half-warp loads: contiguous 512 B run; each quadrant store per
// half-warp: contiguous 256 B run; a full warp covers contiguous 1 KiB per
// output row. All sectors full.

static constexpr int C_ = 256;              // 64 features * 4
static constexpr int F4_PER_PIX_OUT = 16;   // 64 feat / 4
static constexpr unsigned N_THREADS = 8u * 256u * 256u * 16u;  // B*X*Y*16

__global__ __launch_bounds__(256)
void pixelshuffle_kernel(const float4* __restrict__ in, float4* __restrict__ out) {
    unsigned g = blockIdx.x * blockDim.x + threadIdx.x;
    unsigned t     = g & 15u;    // 0..15: feature-quad index
    unsigned pixel = g >> 4;     // input pixel id, < B*X*Y = 2^19

    unsigned y  = pixel & 255u;          // Y_-1
    unsigned bx = pixel >> 8;            // b*256 + x  (b*X + x)

    // Input: pixel row is 64 float4s; thread t reads 4 consecutive float4s.
    const float4* src = in + pixel * (C_ / 4) + t * 4u;
    float4 v0 = __ldcs(src + 0);   // feature 4t+0, quadrants in .x/.y/.z/.w
    float4 v1 = __ldcs(src + 1);   // feature 4t+1
    float4 v2 = __ldcs(src + 2);   // feature 4t+2
    float4 v3 = __ldcs(src + 3);   // feature 4t+3

    // Output float4 index: ((b*512 + 2x+i)*512 + 2y+j)*16 + t
    //  = (2*bx + i)*8192 + (2y + j)*16 + t      (all fits in u32: max ~2^27)
    unsigned ob = (2u * bx) * 8192u + (2u * y) * 16u + t;
    const unsigned ROW = 8192u;  // one output row of float4s (512*16)

    // quadrant component index = 2i + j
    __stcs(out + ob,            make_float4(v0.x, v1.x, v2.x, v3.x)); // i=0, j=0
    __stcs(out + ob + 16,       make_float4(v0.y, v1.y, v2.y, v3.y)); // i=0, j=1
    __stcs(out + ob + ROW,      make_float4(v0.z, v1.z, v2.z, v3.z)); // i=1, j=0
    __stcs(out + ob + ROW + 16, make_float4(v0.w, v1.w, v2.w, v3.w)); // i=1, j=1
}

extern "C" void kernel_launch(void* const* d_in, const int* in_sizes, int n_in,
                              void* d_out, int out_size) {
    const float4* in = (const float4*)d_in[0];
    float4* out = (float4*)d_out;
    pixelshuffle_kernel<<<N_THREADS / 256u, 256u>>>(in, out);
}